// round 2
// baseline (speedup 1.0000x reference)
#include <cuda_runtime.h>

#define N_NODES 50000
#define N_EDGES 800000
#define HIDDEN  128
#define MSG     64
#define KTOT    192
#define XS_STRIDE 257   // 257 % 32 == 1 -> conflict-free column access

// Scratch: per-(etype,node) float sums [2][N][128] and edge counts [2][N].
__device__ float4 g_acc[2 * N_NODES * (HIDDEN / 4)];
__device__ int    g_cnt[2 * N_NODES];

__device__ __forceinline__ float sigm(float x) { return 1.0f / (1.0f + expf(-x)); }

// Vectorized global reduction: one RED.E.ADD.F32.V4 instead of 4 scalar REDs.
__device__ __forceinline__ void red_add_v4(float* addr, float4 v) {
    asm volatile("red.global.add.v4.f32 [%0], {%1, %2, %3, %4};"
                 :: "l"(addr), "f"(v.x), "f"(v.y), "f"(v.z), "f"(v.w)
                 : "memory");
}

// ---------------------------------------------------------------------------
// K0: zero the accumulators (graph replays require re-zero each call)
// ---------------------------------------------------------------------------
__global__ void zero_kernel() {
    int i = blockIdx.x * blockDim.x + threadIdx.x;
    const int total4 = 2 * N_NODES * (HIDDEN / 4);
    if (i < total4) g_acc[i] = make_float4(0.f, 0.f, 0.f, 0.f);
    if (i < 2 * N_NODES) g_cnt[i] = 0;
}

// ---------------------------------------------------------------------------
// K1: edge scatter. One warp per (etype, edge). Lane l handles floats 4l..4l+3.
// feat row gather is fully coalesced (4 lines/warp); reductions hit
// consecutive addresses (vector RED, 4 lines per warp). feat + acc fit in L2.
// ---------------------------------------------------------------------------
__global__ void scatter_kernel(const float4* __restrict__ feat4,
                               const int* __restrict__ src0, const int* __restrict__ dst0,
                               const int* __restrict__ src1, const int* __restrict__ dst1) {
    int gw   = (blockIdx.x * blockDim.x + threadIdx.x) >> 5;
    int lane = threadIdx.x & 31;
    if (gw >= 2 * N_EDGES) return;
    int et = (gw >= N_EDGES);
    int e  = et ? gw - N_EDGES : gw;
    const int* sA = et ? src1 : src0;
    const int* dA = et ? dst1 : dst0;
    int s = __ldg(sA + e);
    int d = __ldg(dA + e);
    float4 v = __ldg(feat4 + s * 32 + lane);
    float* b = reinterpret_cast<float*>(g_acc + (et * N_NODES + d) * 32 + lane);
    red_add_v4(b, v);
    if (lane == 0) atomicAdd(g_cnt + et * N_NODES + d, 1);
}

// ---------------------------------------------------------------------------
// K2: fused mean/combine + GEMM (gates = [feat,G] @ [W_ih;W_hh]^T + biases)
//     + LSTM cell epilogue. Block = 256 threads = 8 warps = 32 nodes.
//
// GEMM mapping: node -> lane, warp w owns gates [32w, 32w+32).
//   - W reads are lane-UNIFORM (broadcast, nL=1) -> no scattered-LDG wavefronts
//   - X reads are LDS with row stride 257 (== 1 mod 32) -> conflict-free
// S[node][0:192] holds X during the GEMM; after a __syncthreads it is reused
// to hold gates[0:256] (aliasing keeps smem small -> good occupancy).
// ---------------------------------------------------------------------------
__global__ void __launch_bounds__(256)
node_kernel(const float4* __restrict__ feat4,
            const float4* __restrict__ Wih4,   // [256][32] float4 (row = gate)
            const float4* __restrict__ Whh4,   // [256][16] float4
            const float*  __restrict__ bih,
            const float*  __restrict__ bhh,
            float* __restrict__ out) {
    __shared__ float S [32][XS_STRIDE];
    __shared__ float Rs[32][MSG];

    int w    = threadIdx.x >> 5;
    int lane = threadIdx.x & 31;
    int base = blockIdx.x * 32;

    // ---- Phase 1: per-node aggregation finalize; warp w handles 4 nodes ----
    #pragma unroll
    for (int nd = 0; nd < 4; nd++) {
        int nl = w * 4 + nd;
        int n  = base + nl;
        if (n < N_NODES) {
            float4 s0 = g_acc[n * 32 + lane];
            float4 s1 = g_acc[(N_NODES + n) * 32 + lane];
            int   c0 = g_cnt[n], c1 = g_cnt[N_NODES + n];
            float i0 = 1.0f / fmaxf((float)c0, 1.0f);
            float i1 = 1.0f / fmaxf((float)c1, 1.0f);
            float ia = 1.0f / fmaxf((float)((c0 > 0) + (c1 > 0)), 1.0f);
            float4 r;
            r.x = (s0.x * i0 + s1.x * i1) * ia;
            r.y = (s0.y * i0 + s1.y * i1) * ia;
            r.z = (s0.z * i0 + s1.z * i1) * ia;
            r.w = (s0.w * i0 + s1.w * i1) * ia;
            float4 fv = feat4[n * 32 + lane];
            int c = lane * 4;
            S[nl][c + 0] = fv.x; S[nl][c + 1] = fv.y;
            S[nl][c + 2] = fv.z; S[nl][c + 3] = fv.w;
            if (lane < 16) {                       // G_t = rst[0:64] -> X[128:192]
                int c2 = 128 + lane * 4;
                S[nl][c2 + 0] = r.x; S[nl][c2 + 1] = r.y;
                S[nl][c2 + 2] = r.z; S[nl][c2 + 3] = r.w;
            } else {                               // R_t = rst[64:128]
                int c2 = (lane - 16) * 4;
                Rs[nl][c2 + 0] = r.x; Rs[nl][c2 + 1] = r.y;
                Rs[nl][c2 + 2] = r.z; Rs[nl][c2 + 3] = r.w;
            }
        } else {
            for (int c = lane; c < KTOT; c += 32) S[nl][c] = 0.0f;
        }
    }
    __syncthreads();

    // ---- Phase 2: GEMM. acc[gi] = gates[node=lane][g0+gi] ----
    float acc[32];
    int g0 = w * 32;
    #pragma unroll
    for (int gi = 0; gi < 32; gi++)
        acc[gi] = __ldg(bih + g0 + gi) + __ldg(bhh + g0 + gi);

    // feat part: K = 128 against W_ih
    #pragma unroll 4
    for (int k4 = 0; k4 < 32; k4++) {
        float x0 = S[lane][k4 * 4 + 0];
        float x1 = S[lane][k4 * 4 + 1];
        float x2 = S[lane][k4 * 4 + 2];
        float x3 = S[lane][k4 * 4 + 3];
        #pragma unroll
        for (int gi = 0; gi < 32; gi++) {
            float4 wv = __ldg(Wih4 + (g0 + gi) * 32 + k4);
            acc[gi] += wv.x * x0 + wv.y * x1 + wv.z * x2 + wv.w * x3;
        }
    }
    // G_t part: K = 64 against W_hh
    #pragma unroll 4
    for (int k4 = 0; k4 < 16; k4++) {
        float x0 = S[lane][128 + k4 * 4 + 0];
        float x1 = S[lane][128 + k4 * 4 + 1];
        float x2 = S[lane][128 + k4 * 4 + 2];
        float x3 = S[lane][128 + k4 * 4 + 3];
        #pragma unroll
        for (int gi = 0; gi < 32; gi++) {
            float4 wv = __ldg(Whh4 + (g0 + gi) * 16 + k4);
            acc[gi] += wv.x * x0 + wv.y * x1 + wv.z * x2 + wv.w * x3;
        }
    }

    __syncthreads();   // all warps done READING X -> safe to alias S with gates
    #pragma unroll
    for (int gi = 0; gi < 32; gi++)
        S[lane][g0 + gi] = acc[gi];
    __syncthreads();

    // ---- Phase 3: LSTM cell epilogue. thread -> (node = t>>3, 8 m-values) ----
    int node = threadIdx.x >> 3;
    int m0   = (threadIdx.x & 7) * 8;
    int n    = base + node;
    if (n < N_NODES) {
        #pragma unroll
        for (int j = 0; j < 8; j++) {
            int m = m0 + j;
            float iG = S[node][m];
            float fG = S[node][64 + m];
            float gG = S[node][128 + m];
            float oG = S[node][192 + m];
            float R  = Rs[node][m];
            float c1v = sigm(fG) * R + sigm(iG) * tanhf(gG);
            float h1v = sigm(oG) * tanhf(c1v);
            out[n * 128 + m]      = h1v;   // h1 in cols [0:64)
            out[n * 128 + 64 + m] = c1v;   // c1 in cols [64:128)
        }
    }
}

// ---------------------------------------------------------------------------
extern "C" void kernel_launch(void* const* d_in, const int* in_sizes, int n_in,
                              void* d_out, int out_size) {
    const float* feat = (const float*)d_in[0];
    const int*   src0 = (const int*)  d_in[1];
    const int*   dst0 = (const int*)  d_in[2];
    const int*   src1 = (const int*)  d_in[3];
    const int*   dst1 = (const int*)  d_in[4];
    const float* Wih  = (const float*)d_in[5];
    const float* Whh  = (const float*)d_in[6];
    const float* bih  = (const float*)d_in[7];
    const float* bhh  = (const float*)d_in[8];
    float* out = (float*)d_out;

    const int total4 = 2 * N_NODES * (HIDDEN / 4);
    zero_kernel<<<(total4 + 1023) / 1024, 1024>>>();

    scatter_kernel<<<(2 * N_EDGES * 32) / 256, 256>>>(
        (const float4*)feat, src0, dst0, src1, dst1);

    node_kernel<<<(N_NODES + 31) / 32, 256>>>(
        (const float4*)feat, (const float4*)Wih, (const float4*)Whh,
        bih, bhh, out);
}

// round 3
// speedup vs baseline: 1.2463x; 1.2463x over previous
#include <cuda_runtime.h>

#define N_NODES 50000
#define N_EDGES 800000
#define HIDDEN  128
#define MSG     64
#define KTOT    192
#define XS_STRIDE 257   // 257 % 32 == 1 -> conflict-free column access

#define N2      (2 * N_NODES)                 // 100000 (etype, node) pairs
#define SCAN_B  1024
#define SCAN_NB ((N2 + SCAN_B - 1) / SCAN_B)  // 98

// CSR scratch
__device__ int g_cnt[N2];
__device__ int g_off[N2];
__device__ int g_cur[N2];
__device__ int g_bsum[SCAN_NB];
__device__ int g_elist[2 * N_EDGES];

__device__ __forceinline__ float sigm(float x) { return 1.0f / (1.0f + expf(-x)); }

// ---------------------------------------------------------------------------
// K0: zero histogram counters (graph replays require re-zero each call)
// ---------------------------------------------------------------------------
__global__ void zero_kernel() {
    int i = blockIdx.x * blockDim.x + threadIdx.x;
    if (i < N2) g_cnt[i] = 0;
}

// ---------------------------------------------------------------------------
// K1: degree histogram. 1 thread per (etype, edge); distinct-address atomics.
// ---------------------------------------------------------------------------
__global__ void hist_kernel(const int* __restrict__ dst0,
                            const int* __restrict__ dst1) {
    int i = blockIdx.x * blockDim.x + threadIdx.x;
    if (i >= 2 * N_EDGES) return;
    int et = (i >= N_EDGES);
    int e  = et ? i - N_EDGES : i;
    int d  = __ldg(et ? dst1 + e : dst0 + e);
    atomicAdd(&g_cnt[et * N_NODES + d], 1);
}

// ---------------------------------------------------------------------------
// K2a/b/c: exclusive scan over g_cnt -> g_off (and init g_cur)
// ---------------------------------------------------------------------------
__global__ void scan1_kernel() {
    __shared__ int sh[SCAN_B];
    int t = threadIdx.x;
    int i = blockIdx.x * SCAN_B + t;
    int v = (i < N2) ? g_cnt[i] : 0;
    sh[t] = v;
    __syncthreads();
    #pragma unroll
    for (int ofs = 1; ofs < SCAN_B; ofs <<= 1) {
        int x = (t >= ofs) ? sh[t - ofs] : 0;
        __syncthreads();
        sh[t] += x;
        __syncthreads();
    }
    if (i < N2) g_off[i] = sh[t] - v;        // exclusive
    if (t == SCAN_B - 1) g_bsum[blockIdx.x] = sh[t];
}

__global__ void scan2_kernel() {
    if (threadIdx.x == 0) {
        int s = 0;
        for (int b = 0; b < SCAN_NB; b++) { int v = g_bsum[b]; g_bsum[b] = s; s += v; }
    }
}

__global__ void scan3_kernel() {
    int i = blockIdx.x * blockDim.x + threadIdx.x;
    if (i < N2) {
        int o = g_off[i] + g_bsum[i / SCAN_B];
        g_off[i] = o;
        g_cur[i] = o;
    }
}

// ---------------------------------------------------------------------------
// K3: fill CSR edge lists (src ids grouped by (etype,dst))
// ---------------------------------------------------------------------------
__global__ void fill_kernel(const int* __restrict__ src0, const int* __restrict__ dst0,
                            const int* __restrict__ src1, const int* __restrict__ dst1) {
    int i = blockIdx.x * blockDim.x + threadIdx.x;
    if (i >= 2 * N_EDGES) return;
    int et = (i >= N_EDGES);
    int e  = et ? i - N_EDGES : i;
    int d  = __ldg(et ? dst1 + e : dst0 + e);
    int s  = __ldg(et ? src1 + e : src0 + e);
    int pos = atomicAdd(&g_cur[et * N_NODES + d], 1);
    g_elist[pos] = s;
}

// ---------------------------------------------------------------------------
// K4: fused CSR gather + mean/combine + GEMM + LSTM cell.
// Block = 256 threads = 8 warps = 32 nodes.
//   Phase 1: warp w gathers edge lists for its 4 nodes (register float4 sums,
//            coalesced 512B feat-row reads, no atomics), builds X in smem.
//   Phase 2: GEMM gates = [feat,G] @ [W_ih;W_hh]^T. node -> lane so W loads
//            are lane-uniform broadcasts; X via conflict-free LDS (stride 257).
//   Phase 3: LSTM cell epilogue.
// ---------------------------------------------------------------------------
__global__ void __launch_bounds__(256)
node_kernel(const float4* __restrict__ feat4,
            const float4* __restrict__ Wih4,   // [256][32] float4 (row = gate)
            const float4* __restrict__ Whh4,   // [256][16] float4
            const float*  __restrict__ bih,
            const float*  __restrict__ bhh,
            float* __restrict__ out) {
    __shared__ float S [32][XS_STRIDE];
    __shared__ float Rs[32][MSG];

    int w    = threadIdx.x >> 5;
    int lane = threadIdx.x & 31;
    int base = blockIdx.x * 32;

    // ---- Phase 1: gather + finalize; warp w handles 4 nodes ----
    #pragma unroll
    for (int nd = 0; nd < 4; nd++) {
        int nl = w * 4 + nd;
        int n  = base + nl;
        if (n < N_NODES) {
            float4 r;
            {
                float4 a0 = make_float4(0.f, 0.f, 0.f, 0.f);
                float4 a1 = a0, b0 = a0, b1 = a0;
                int o0 = g_off[n],           c0 = g_cnt[n];
                int o1 = g_off[N_NODES + n], c1 = g_cnt[N_NODES + n];
                int e = o0, end = o0 + c0;
                for (; e + 1 < end; e += 2) {
                    int s0 = g_elist[e], s1 = g_elist[e + 1];
                    float4 v0 = __ldg(feat4 + s0 * 32 + lane);
                    float4 v1 = __ldg(feat4 + s1 * 32 + lane);
                    a0.x += v0.x; a0.y += v0.y; a0.z += v0.z; a0.w += v0.w;
                    a1.x += v1.x; a1.y += v1.y; a1.z += v1.z; a1.w += v1.w;
                }
                if (e < end) {
                    float4 v0 = __ldg(feat4 + g_elist[e] * 32 + lane);
                    a0.x += v0.x; a0.y += v0.y; a0.z += v0.z; a0.w += v0.w;
                }
                e = o1; end = o1 + c1;
                for (; e + 1 < end; e += 2) {
                    int s0 = g_elist[e], s1 = g_elist[e + 1];
                    float4 v0 = __ldg(feat4 + s0 * 32 + lane);
                    float4 v1 = __ldg(feat4 + s1 * 32 + lane);
                    b0.x += v0.x; b0.y += v0.y; b0.z += v0.z; b0.w += v0.w;
                    b1.x += v1.x; b1.y += v1.y; b1.z += v1.z; b1.w += v1.w;
                }
                if (e < end) {
                    float4 v0 = __ldg(feat4 + g_elist[e] * 32 + lane);
                    b0.x += v0.x; b0.y += v0.y; b0.z += v0.z; b0.w += v0.w;
                }
                float i0 = 1.0f / fmaxf((float)c0, 1.0f);
                float i1 = 1.0f / fmaxf((float)c1, 1.0f);
                float ia = 1.0f / fmaxf((float)((c0 > 0) + (c1 > 0)), 1.0f);
                r.x = ((a0.x + a1.x) * i0 + (b0.x + b1.x) * i1) * ia;
                r.y = ((a0.y + a1.y) * i0 + (b0.y + b1.y) * i1) * ia;
                r.z = ((a0.z + a1.z) * i0 + (b0.z + b1.z) * i1) * ia;
                r.w = ((a0.w + a1.w) * i0 + (b0.w + b1.w) * i1) * ia;
            }
            float4 fv = __ldg(feat4 + n * 32 + lane);
            int c = lane * 4;
            S[nl][c + 0] = fv.x; S[nl][c + 1] = fv.y;
            S[nl][c + 2] = fv.z; S[nl][c + 3] = fv.w;
            if (lane < 16) {                       // G_t = rst[0:64] -> X[128:192]
                int c2 = 128 + lane * 4;
                S[nl][c2 + 0] = r.x; S[nl][c2 + 1] = r.y;
                S[nl][c2 + 2] = r.z; S[nl][c2 + 3] = r.w;
            } else {                               // R_t = rst[64:128]
                int c2 = (lane - 16) * 4;
                Rs[nl][c2 + 0] = r.x; Rs[nl][c2 + 1] = r.y;
                Rs[nl][c2 + 2] = r.z; Rs[nl][c2 + 3] = r.w;
            }
        } else {
            for (int c = lane; c < KTOT; c += 32) S[nl][c] = 0.0f;
        }
    }
    __syncthreads();

    // ---- Phase 2: GEMM. acc[gi] = gates[node=lane][g0+gi] ----
    float acc[32];
    int g0 = w * 32;
    #pragma unroll
    for (int gi = 0; gi < 32; gi++)
        acc[gi] = __ldg(bih + g0 + gi) + __ldg(bhh + g0 + gi);

    // feat part: K = 128 against W_ih
    #pragma unroll 4
    for (int k4 = 0; k4 < 32; k4++) {
        float x0 = S[lane][k4 * 4 + 0];
        float x1 = S[lane][k4 * 4 + 1];
        float x2 = S[lane][k4 * 4 + 2];
        float x3 = S[lane][k4 * 4 + 3];
        #pragma unroll
        for (int gi = 0; gi < 32; gi++) {
            float4 wv = __ldg(Wih4 + (g0 + gi) * 32 + k4);
            acc[gi] += wv.x * x0 + wv.y * x1 + wv.z * x2 + wv.w * x3;
        }
    }
    // G_t part: K = 64 against W_hh
    #pragma unroll 4
    for (int k4 = 0; k4 < 16; k4++) {
        float x0 = S[lane][128 + k4 * 4 + 0];
        float x1 = S[lane][128 + k4 * 4 + 1];
        float x2 = S[lane][128 + k4 * 4 + 2];
        float x3 = S[lane][128 + k4 * 4 + 3];
        #pragma unroll
        for (int gi = 0; gi < 32; gi++) {
            float4 wv = __ldg(Whh4 + (g0 + gi) * 16 + k4);
            acc[gi] += wv.x * x0 + wv.y * x1 + wv.z * x2 + wv.w * x3;
        }
    }

    __syncthreads();   // all warps done READING X -> safe to alias S with gates
    #pragma unroll
    for (int gi = 0; gi < 32; gi++)
        S[lane][g0 + gi] = acc[gi];
    __syncthreads();

    // ---- Phase 3: LSTM cell epilogue. thread -> (node = t>>3, 8 m-values) ----
    int node = threadIdx.x >> 3;
    int m0   = (threadIdx.x & 7) * 8;
    int n    = base + node;
    if (n < N_NODES) {
        #pragma unroll
        for (int j = 0; j < 8; j++) {
            int m = m0 + j;
            float iG = S[node][m];
            float fG = S[node][64 + m];
            float gG = S[node][128 + m];
            float oG = S[node][192 + m];
            float R  = Rs[node][m];
            float c1v = sigm(fG) * R + sigm(iG) * tanhf(gG);
            float h1v = sigm(oG) * tanhf(c1v);
            out[n * 128 + m]      = h1v;   // h1 in cols [0:64)
            out[n * 128 + 64 + m] = c1v;   // c1 in cols [64:128)
        }
    }
}

// ---------------------------------------------------------------------------
extern "C" void kernel_launch(void* const* d_in, const int* in_sizes, int n_in,
                              void* d_out, int out_size) {
    const float* feat = (const float*)d_in[0];
    const int*   src0 = (const int*)  d_in[1];
    const int*   dst0 = (const int*)  d_in[2];
    const int*   src1 = (const int*)  d_in[3];
    const int*   dst1 = (const int*)  d_in[4];
    const float* Wih  = (const float*)d_in[5];
    const float* Whh  = (const float*)d_in[6];
    const float* bih  = (const float*)d_in[7];
    const float* bhh  = (const float*)d_in[8];
    float* out = (float*)d_out;

    const int epb = (2 * N_EDGES + 255) / 256;

    zero_kernel <<<(N2 + 1023) / 1024, 1024>>>();
    hist_kernel <<<epb, 256>>>(dst0, dst1);
    scan1_kernel<<<SCAN_NB, SCAN_B>>>();
    scan2_kernel<<<1, 32>>>();
    scan3_kernel<<<(N2 + 1023) / 1024, 1024>>>();
    fill_kernel <<<epb, 256>>>(src0, dst0, src1, dst1);

    node_kernel<<<(N_NODES + 31) / 32, 256>>>(
        (const float4*)feat, (const float4*)Wih, (const float4*)Whh,
        bih, bhh, out);
}